// round 15
// baseline (speedup 1.0000x reference)
#include <cuda_runtime.h>
#include <cuda_fp16.h>
#include <cstdint>

#define NN 100000
#define NE 1600000
#define NL 200000
#define DH  128
#define DOUT 64
#define MEGA_BLOCKS 444
#define MEGA_THREADS 256
#define MEGA_WARPS (MEGA_BLOCKS * 8)

// ====================== scratch (device globals) =============================
__device__ __align__(16) int   g_deg[NN];
__device__ __align__(16) float g_dinv[NN];
__device__ __align__(16) float g_invdeg[NN];
__device__ __align__(16) int   g_off[NN + 1];
__device__ __align__(16) int   g_cursor[NN];
__device__ __align__(16) int2  g_csrn[NE];               // {src, norm bits}
__device__ __align__(16) int   g_bsum[128];
__device__ __align__(16) __half g_h1[(size_t)NN * DH];
__device__ __align__(16) __half g_z [(size_t)NN * DH];
__device__ __align__(16) __half g_h2[(size_t)NN * DOUT];
__device__ __align__(16) __half g_z2[(size_t)NN * DOUT];
__device__ __align__(16) uint2 g_wf1[8 * 16 * 32];
__device__ __align__(16) uint2 g_wf2[8 * 8 * 32];
// grid barrier state (count returns to 0 after each barrier; gen monotonic)
__device__ int g_bar_count = 0;
__device__ int g_bar_gen   = 0;

// ====================== small helpers ========================================
__device__ __forceinline__ uint32_t smem_u32(const void* p) {
    uint32_t a;
    asm("{ .reg .u64 t; cvta.to.shared.u64 t, %1; cvt.u32.u64 %0, t; }" : "=r"(a) : "l"(p));
    return a;
}
__device__ __forceinline__ void ldmx4(uint32_t* r, uint32_t addr) {
    asm volatile("ldmatrix.sync.aligned.m8n8.x4.shared.b16 {%0,%1,%2,%3}, [%4];"
                 : "=r"(r[0]), "=r"(r[1]), "=r"(r[2]), "=r"(r[3]) : "r"(addr));
}
__device__ __forceinline__ void mma16816h(float* c, const uint32_t* a, const uint32_t* b) {
    asm volatile(
        "mma.sync.aligned.m16n8k16.row.col.f32.f16.f16.f32 "
        "{%0,%1,%2,%3}, {%4,%5,%6,%7}, {%8,%9}, {%0,%1,%2,%3};"
        : "+f"(c[0]), "+f"(c[1]), "+f"(c[2]), "+f"(c[3])
        : "r"(a[0]), "r"(a[1]), "r"(a[2]), "r"(a[3]), "r"(b[0]), "r"(b[1]));
}
__device__ __forceinline__ uint32_t packh2(float a, float b) {
    __half2 p = __floats2half2_rn(a, b);
    return *(uint32_t*)&p;
}
__device__ __forceinline__ void grid_barrier() {
    __syncthreads();
    if (threadIdx.x == 0) {
        __threadfence();
        int gen = *(volatile int*)&g_bar_gen;
        if (atomicAdd(&g_bar_count, 1) == MEGA_BLOCKS - 1) {
            g_bar_count = 0;
            __threadfence();
            atomicExch(&g_bar_gen, gen + 1);
        } else {
            while (*(volatile int*)&g_bar_gen == gen) {}
        }
        __threadfence();
    }
    __syncthreads();
}

// ====================== setup kernels (R12 form) ==============================
__global__ void k_degree(const int* __restrict__ ei) {
    int e = blockIdx.x * blockDim.x + threadIdx.x;
    if (e < NE) atomicAdd(&g_deg[ei[NE + e]], 1);
}
__global__ void k_scan1(int n) {
    __shared__ int wsum[32];
    int t = threadIdx.x;
    int gid = blockIdx.x * 1024 + t;
    int v = (gid < n) ? g_deg[gid] : 0;
    if (gid < n) {
        float d = (float)(v + 1);
        g_dinv[gid]   = rsqrtf(d);
        g_invdeg[gid] = 1.0f / d;
    }
    int x = v;
    #pragma unroll
    for (int o = 1; o < 32; o <<= 1) {
        int y = __shfl_up_sync(0xffffffffu, x, o);
        if ((t & 31) >= o) x += y;
    }
    if ((t & 31) == 31) wsum[t >> 5] = x;
    __syncthreads();
    if (t < 32) {
        int w = wsum[t];
        int xx = w;
        #pragma unroll
        for (int o = 1; o < 32; o <<= 1) {
            int y = __shfl_up_sync(0xffffffffu, xx, o);
            if (t >= o) xx += y;
        }
        wsum[t] = xx - w;
    }
    __syncthreads();
    int excl = x - v + wsum[t >> 5];
    if (gid < n) g_off[gid] = excl;
    if (t == 1023) g_bsum[blockIdx.x] = excl + v;
}
__global__ void k_scan3(int n, int nb) {
    __shared__ int s[128];
    int t = threadIdx.x;
    if (t < 128) s[t] = (t < nb) ? g_bsum[t] : 0;
    __syncthreads();
    #pragma unroll
    for (int o = 1; o < 128; o <<= 1) {
        int x = 0;
        if (t < 128 && t >= o) x = s[t - o];
        __syncthreads();
        if (t < 128) s[t] += x;
        __syncthreads();
    }
    int base = (blockIdx.x == 0) ? 0 : s[blockIdx.x - 1];
    int gid = blockIdx.x * 1024 + t;
    if (gid < n) {
        int v = g_off[gid] + base;
        g_off[gid]    = v;
        g_cursor[gid] = v;
    }
    if (gid == 0) g_off[n] = NE;
}
__global__ void k_scatter(const int* __restrict__ ei) {
    int e = blockIdx.x * blockDim.x + threadIdx.x;
    if (e < NE) {
        int s = ei[e];
        int d = ei[NE + e];
        float nm = g_dinv[s] * g_dinv[d];
        int p = atomicAdd(&g_cursor[d], 1);
        g_csrn[p] = make_int2(s, __float_as_int(nm));
    }
}

// ====================== W prep ================================================
__device__ __forceinline__ void prep_frag(const float* W, uint2* frag, int idx, int N) {
    int NT = N / 8;
    int lane = idx & 31;
    int nt   = (idx >> 5) % NT;
    int ks   = idx / (32 * NT);
    int n = nt * 8 + (lane >> 2);
    int k = ks * 16 + (lane & 3) * 2;
    uint2 o;
    o.x = packh2(W[(k    ) * N + n], W[(k + 1) * N + n]);
    o.y = packh2(W[(k + 8) * N + n], W[(k + 9) * N + n]);
    frag[idx] = o;
}
__global__ void k_prepw_all(const float* __restrict__ W1, uint2* __restrict__ f1,
                            const float* __restrict__ W2, uint2* __restrict__ f2) {
    int idx = blockIdx.x * blockDim.x + threadIdx.x;
    const int N1 = 8 * 16 * 32;
    const int N2 = 8 * 8 * 32;
    if (idx < N1) prep_frag(W1, f1, idx, 128);
    else if (idx < N1 + N2) prep_frag(W2, f2, idx - N1, 64);
}

// ====================== gemm1 (unchanged, R12) ================================
__global__ void __launch_bounds__(256, 3) k_gemm1(
    const float* __restrict__ A,
    const uint2* __restrict__ Wf,
    __half* __restrict__ C, int M) {
    const int N = 128, SP = 136, NS = 4, NT = 16;
    extern __shared__ __align__(16) __half sm[];
    __half* As = sm;

    int tid = threadIdx.x, lane = tid & 31, wid = tid >> 5;
    int row0 = blockIdx.x * 64;

    #pragma unroll
    for (int i = tid; i < 2048; i += 256) {
        int r  = i >> 5;
        int c4 = (i & 31) << 2;
        int row = row0 + r;
        float4 v = (row < M) ? *(const float4*)(A + (size_t)row * 128 + c4)
                             : make_float4(0.f, 0.f, 0.f, 0.f);
        *(uint2*)(As + r * SP + c4) = make_uint2(packh2(v.x, v.y), packh2(v.z, v.w));
    }
    __syncthreads();

    int wm  = (wid >> 2) * 32;
    int wnt = (wid & 3) * NS;

    float acc[2][NS][4];
    #pragma unroll
    for (int ms = 0; ms < 2; ms++)
        #pragma unroll
        for (int ns = 0; ns < NS; ns++)
            #pragma unroll
            for (int q = 0; q < 4; q++) acc[ms][ns][q] = 0.f;

    uint32_t base_a = smem_u32(As);

    #pragma unroll
    for (int k0 = 0; k0 < 128; k0 += 16) {
        int ks = k0 >> 4;
        uint32_t a[2][4];
        #pragma unroll
        for (int ms = 0; ms < 2; ms++) {
            int ar = wm + ms * 16 + (lane & 15);
            int ac = k0 + (lane >> 4) * 8;
            uint32_t off = (uint32_t)(ar * SP + ac) * 2;
            ldmx4(a[ms], base_a + off);
        }
        const uint2* fp = Wf + ((size_t)ks * NT + wnt) * 32 + lane;
        #pragma unroll
        for (int ns = 0; ns < NS; ns++) {
            uint2 f = __ldg(fp + ns * 32);
            uint32_t b[2] = {f.x, f.y};
            mma16816h(acc[0][ns], a[0], b);
            mma16816h(acc[1][ns], a[1], b);
        }
    }

    int gID = lane >> 2, tig = lane & 3;
    #pragma unroll
    for (int ms = 0; ms < 2; ms++) {
        int r0 = row0 + wm + ms * 16 + gID;
        #pragma unroll
        for (int ns = 0; ns < NS; ns++) {
            int col = (wnt + ns) * 8 + tig * 2;
            if (r0 < M)
                *(__half2*)(C + (size_t)r0 * N + col) =
                    __floats2half2_rn(acc[ms][ns][0], acc[ms][ns][1]);
            if (r0 + 8 < M)
                *(__half2*)(C + (size_t)(r0 + 8) * N + col) =
                    __floats2half2_rn(acc[ms][ns][2], acc[ms][ns][3]);
        }
    }
}

// ====================== device fn: aggregate one node (R12 agg body) =========
template <int D, bool RELU>
__device__ __forceinline__ void agg_node(
    const __half* __restrict__ h, const float* __restrict__ bias,
    __half* __restrict__ zo, int w, int lane) {
    const int V = D / 32;
    int beg = g_off[w], end = g_off[w + 1];
    float acc[V];
    #pragma unroll
    for (int i = 0; i < V; i++) acc[i] = 0.0f;

    for (int bb = beg; bb < end; bb += 32) {
        int e = bb + lane;
        int2 sn = (e < end) ? g_csrn[e] : make_int2(0, 0);
        int s = sn.x;
        float nm = __int_as_float(sn.y);
        int cnt = min(32, end - bb);
        int j = 0;
        for (; j + 3 < cnt; j += 4) {
            int   s0 = __shfl_sync(0xffffffffu, s,  j);
            float n0 = __shfl_sync(0xffffffffu, nm, j);
            int   s1 = __shfl_sync(0xffffffffu, s,  j + 1);
            float n1 = __shfl_sync(0xffffffffu, nm, j + 1);
            int   s2 = __shfl_sync(0xffffffffu, s,  j + 2);
            float n2 = __shfl_sync(0xffffffffu, nm, j + 2);
            int   s3 = __shfl_sync(0xffffffffu, s,  j + 3);
            float n3 = __shfl_sync(0xffffffffu, nm, j + 3);
            if (V == 4) {
                uint2 u0 = *(const uint2*)(h + (size_t)s0 * D + lane * 4);
                uint2 u1 = *(const uint2*)(h + (size_t)s1 * D + lane * 4);
                uint2 u2 = *(const uint2*)(h + (size_t)s2 * D + lane * 4);
                uint2 u3 = *(const uint2*)(h + (size_t)s3 * D + lane * 4);
                float2 a0 = __half22float2(*(__half2*)&u0.x), b0 = __half22float2(*(__half2*)&u0.y);
                float2 a1 = __half22float2(*(__half2*)&u1.x), b1 = __half22float2(*(__half2*)&u1.y);
                float2 a2 = __half22float2(*(__half2*)&u2.x), b2 = __half22float2(*(__half2*)&u2.y);
                float2 a3 = __half22float2(*(__half2*)&u3.x), b3 = __half22float2(*(__half2*)&u3.y);
                acc[0] += a0.x * n0; acc[1] += a0.y * n0; acc[2] += b0.x * n0; acc[3] += b0.y * n0;
                acc[0] += a1.x * n1; acc[1] += a1.y * n1; acc[2] += b1.x * n1; acc[3] += b1.y * n1;
                acc[0] += a2.x * n2; acc[1] += a2.y * n2; acc[2] += b2.x * n2; acc[3] += b2.y * n2;
                acc[0] += a3.x * n3; acc[1] += a3.y * n3; acc[2] += b3.x * n3; acc[3] += b3.y * n3;
            } else {
                uint32_t u0 = *(const uint32_t*)(h + (size_t)s0 * D + lane * 2);
                uint32_t u1 = *(const uint32_t*)(h + (size_t)s1 * D + lane * 2);
                uint32_t u2 = *(const uint32_t*)(h + (size_t)s2 * D + lane * 2);
                uint32_t u3 = *(const uint32_t*)(h + (size_t)s3 * D + lane * 2);
                float2 a0 = __half22float2(*(__half2*)&u0);
                float2 a1 = __half22float2(*(__half2*)&u1);
                float2 a2 = __half22float2(*(__half2*)&u2);
                float2 a3 = __half22float2(*(__half2*)&u3);
                acc[0] += a0.x * n0; acc[1] += a0.y * n0;
                acc[0] += a1.x * n1; acc[1] += a1.y * n1;
                acc[0] += a2.x * n2; acc[1] += a2.y * n2;
                acc[0] += a3.x * n3; acc[1] += a3.y * n3;
            }
        }
        for (; j < cnt; j++) {
            int   s0 = __shfl_sync(0xffffffffu, s,  j);
            float n0 = __shfl_sync(0xffffffffu, nm, j);
            const __half* p0 = h + (size_t)s0 * D + lane * V;
            if (V == 4) {
                uint2 u0 = *(const uint2*)p0;
                float2 a0 = __half22float2(*(__half2*)&u0.x);
                float2 b0 = __half22float2(*(__half2*)&u0.y);
                acc[0] += a0.x * n0; acc[1] += a0.y * n0;
                acc[2] += b0.x * n0; acc[3] += b0.y * n0;
            } else {
                uint32_t u0 = *(const uint32_t*)p0;
                float2 a0 = __half22float2(*(__half2*)&u0);
                acc[0] += a0.x * n0; acc[1] += a0.y * n0;
            }
        }
    }

    float inv = g_invdeg[w];
    const __half* hp = h + (size_t)w * D + lane * V;
    const float* bp = bias + lane * V;
    __half* op = zo + (size_t)w * D + lane * V;
    if (V == 4) {
        uint2 su = *(const uint2*)hp;
        float2 s0 = __half22float2(*(__half2*)&su.x);
        float2 s1 = __half22float2(*(__half2*)&su.y);
        float4 bv = *(const float4*)bp;
        float ox = acc[0] + s0.x * inv + bv.x;
        float oy = acc[1] + s0.y * inv + bv.y;
        float oz = acc[2] + s1.x * inv + bv.z;
        float ow = acc[3] + s1.y * inv + bv.w;
        if (RELU) { ox = fmaxf(ox, 0.f); oy = fmaxf(oy, 0.f);
                    oz = fmaxf(oz, 0.f); ow = fmaxf(ow, 0.f); }
        *(uint2*)op = make_uint2(packh2(ox, oy), packh2(oz, ow));
    } else {
        uint32_t su = *(const uint32_t*)hp;
        float2 s0 = __half22float2(*(__half2*)&su);
        float2 bv = *(const float2*)bp;
        float ox = acc[0] + s0.x * inv + bv.x;
        float oy = acc[1] + s0.y * inv + bv.y;
        if (RELU) { ox = fmaxf(ox, 0.f); oy = fmaxf(oy, 0.f); }
        *(uint32_t*)op = packh2(ox, oy);
    }
}

// ====================== mega kernel: agg1 -> gemm2 -> agg2 -> decode =========
__global__ void __launch_bounds__(MEGA_THREADS, 3) k_mega(
    const float* __restrict__ b1, const float* __restrict__ b2,
    const int* __restrict__ eli, float* __restrict__ out) {
    extern __shared__ __align__(16) __half sm[];
    const int SP = 136;
    int tid = threadIdx.x, lane = tid & 31, wid = tid >> 5;
    int gwarp = blockIdx.x * 8 + wid;

    // ---- phase 1: agg1 (z = relu(A h1 + b1)) ----
    for (int w = gwarp; w < NN; w += MEGA_WARPS)
        agg_node<DH, true>(g_h1, b1, g_z, w, lane);
    grid_barrier();

    // ---- phase 2: gemm2 tiles (h2 = z @ W2) ----
    {
        const int NTILES = (NN + 63) / 64;
        int wm  = (wid >> 2) * 32;
        int wnt = (wid & 3) * 2;
        uint32_t base_a = smem_u32(sm);
        for (int t = blockIdx.x; t < NTILES; t += MEGA_BLOCKS) {
            int row0 = t * 64;
            __syncthreads();   // previous tile fully consumed
            #pragma unroll
            for (int i = tid; i < 1024; i += 256) {
                int r  = i >> 4;
                int c8 = (i & 15) << 3;
                int row = row0 + r;
                uint4 v = (row < NN) ? *(const uint4*)(g_z + (size_t)row * 128 + c8)
                                     : make_uint4(0u, 0u, 0u, 0u);
                *(uint4*)(sm + r * SP + c8) = v;
            }
            __syncthreads();

            float acc[2][2][4];
            #pragma unroll
            for (int ms = 0; ms < 2; ms++)
                #pragma unroll
                for (int ns = 0; ns < 2; ns++)
                    #pragma unroll
                    for (int q = 0; q < 4; q++) acc[ms][ns][q] = 0.f;

            #pragma unroll
            for (int k0 = 0; k0 < 128; k0 += 16) {
                int ks = k0 >> 4;
                uint32_t a[2][4];
                #pragma unroll
                for (int ms = 0; ms < 2; ms++) {
                    int ar = wm + ms * 16 + (lane & 15);
                    int ac = k0 + (lane >> 4) * 8;
                    uint32_t off = (uint32_t)(ar * SP + ac) * 2;
                    ldmx4(a[ms], base_a + off);
                }
                const uint2* fp = g_wf2 + ((size_t)ks * 8 + wnt) * 32 + lane;
                #pragma unroll
                for (int ns = 0; ns < 2; ns++) {
                    uint2 f = __ldg(fp + ns * 32);
                    uint32_t b[2] = {f.x, f.y};
                    mma16816h(acc[0][ns], a[0], b);
                    mma16816h(acc[1][ns], a[1], b);
                }
            }

            int gID = lane >> 2, tig = lane & 3;
            #pragma unroll
            for (int ms = 0; ms < 2; ms++) {
                int r0 = row0 + wm + ms * 16 + gID;
                #pragma unroll
                for (int ns = 0; ns < 2; ns++) {
                    int col = (wnt + ns) * 8 + tig * 2;
                    if (r0 < NN)
                        *(__half2*)(g_h2 + (size_t)r0 * DOUT + col) =
                            __floats2half2_rn(acc[ms][ns][0], acc[ms][ns][1]);
                    if (r0 + 8 < NN)
                        *(__half2*)(g_h2 + (size_t)(r0 + 8) * DOUT + col) =
                            __floats2half2_rn(acc[ms][ns][2], acc[ms][ns][3]);
                }
            }
        }
    }
    grid_barrier();

    // ---- phase 3: agg2 (z2 = A h2 + b2) ----
    for (int w = gwarp; w < NN; w += MEGA_WARPS)
        agg_node<DOUT, false>(g_h2, b2, g_z2, w, lane);
    grid_barrier();

    // ---- phase 4: decode ----
    int gtid = blockIdx.x * MEGA_THREADS + tid;
    for (int idx = gtid; idx < NL * 16; idx += MEGA_BLOCKS * MEGA_THREADS) {
        int e = idx >> 4;
        int l = idx & 15;
        int a = eli[e];
        int b = eli[NL + e];
        uint2 ua = *(const uint2*)(g_z2 + (size_t)a * DOUT + l * 4);
        uint2 ub = *(const uint2*)(g_z2 + (size_t)b * DOUT + l * 4);
        float2 a0 = __half22float2(*(__half2*)&ua.x);
        float2 a1 = __half22float2(*(__half2*)&ua.y);
        float2 b0 = __half22float2(*(__half2*)&ub.x);
        float2 b1 = __half22float2(*(__half2*)&ub.y);
        float d = a0.x * b0.x + a0.y * b0.y + a1.x * b1.x + a1.y * b1.y;
        d += __shfl_xor_sync(0xffffffffu, d, 1);
        d += __shfl_xor_sync(0xffffffffu, d, 2);
        d += __shfl_xor_sync(0xffffffffu, d, 4);
        d += __shfl_xor_sync(0xffffffffu, d, 8);
        if (l == 0) out[e] = d;
    }
}

// ====================== launch ===============================================
extern "C" void kernel_launch(void* const* d_in, const int* in_sizes, int n_in,
                              void* d_out, int out_size) {
    const float* x   = (const float*)d_in[0];
    const int*   ei  = (const int*)d_in[1];
    const int*   eli = (const int*)d_in[2];
    const float* W1  = (const float*)d_in[3];
    const float* b1  = (const float*)d_in[4];
    const float* W2  = (const float*)d_in[5];
    const float* b2  = (const float*)d_in[6];
    float* out = (float*)d_out;

    __half *p_h1;
    uint2 *p_wf1, *p_wf2;
    int* p_deg;
    cudaGetSymbolAddress((void**)&p_h1, g_h1);
    cudaGetSymbolAddress((void**)&p_wf1, g_wf1);
    cudaGetSymbolAddress((void**)&p_wf2, g_wf2);
    cudaGetSymbolAddress((void**)&p_deg, g_deg);

    const int SP = 136;
    const int SMEM1 = 64 * SP * 2;    // 17408 B
    cudaFuncSetAttribute(k_gemm1, cudaFuncAttributeMaxDynamicSharedMemorySize, SMEM1);
    cudaFuncSetAttribute(k_mega,  cudaFuncAttributeMaxDynamicSharedMemorySize, SMEM1);

    const int NB_EDGE  = (NE + 255) / 256;
    const int NB_SCAN  = (NN + 1023) / 1024;
    const int NB_GEMM1 = (NN + 63) / 64;

    cudaStream_t s2;
    cudaStreamCreateWithFlags(&s2, cudaStreamNonBlocking);
    cudaEvent_t evF, evJ;
    cudaEventCreateWithFlags(&evF, cudaEventDisableTiming);
    cudaEventCreateWithFlags(&evJ, cudaEventDisableTiming);

    cudaEventRecord(evF, 0);
    cudaStreamWaitEvent(s2, evF, 0);

    // setup chain on s2
    cudaMemsetAsync(p_deg, 0, NN * sizeof(int), s2);
    k_degree<<<NB_EDGE, 256, 0, s2>>>(ei);
    k_scan1<<<NB_SCAN, 1024, 0, s2>>>(NN);
    k_scan3<<<NB_SCAN, 1024, 0, s2>>>(NN, NB_SCAN);
    k_scatter<<<NB_EDGE, 256, 0, s2>>>(ei);
    cudaEventRecord(evJ, s2);

    // main stream: W prep + gemm1
    k_prepw_all<<<(6144 + 255) / 256, 256>>>(W1, p_wf1, W2, p_wf2);
    k_gemm1<<<NB_GEMM1, 256, SMEM1>>>(x, p_wf1, p_h1, NN);

    cudaStreamWaitEvent(0, evJ, 0);

    // fused post-join pipeline (persistent, grid barriers between phases)
    k_mega<<<MEGA_BLOCKS, MEGA_THREADS, SMEM1>>>(b1, b2, eli, out);
}

// round 16
// speedup vs baseline: 1.2646x; 1.2646x over previous
#include <cuda_runtime.h>
#include <cuda_fp16.h>
#include <cstdint>

#define NN 100000
#define NE 1600000
#define NL 200000
#define DH  128
#define DOUT 64
#define NEH 800000   // NE/2

// ====================== scratch (device globals) =============================
__device__ __align__(16) int   g_deg[NN];
__device__ __align__(16) float g_dinv[NN];
__device__ __align__(16) float g_invdeg[NN];
__device__ __align__(16) int   g_off[NN + 1];
__device__ __align__(16) int   g_cursor[NN];
__device__ __align__(16) int2  g_csrn[NE];               // {src, norm bits}
__device__ __align__(16) int   g_bsum[128];
__device__ __align__(16) __half g_h1[(size_t)NN * DH];
__device__ __align__(16) __half g_z [(size_t)NN * DH];
__device__ __align__(16) __half g_h2[(size_t)NN * DOUT];
__device__ __align__(16) __half g_z2[(size_t)NN * DOUT];
// W fragments (fp16), mma-ready: [ks][ntile][lane] -> uint2{b0,b1}
__device__ __align__(16) uint2 g_wf1[8 * 16 * 32];
__device__ __align__(16) uint2 g_wf2[8 * 8 * 32];

// ====================== small helpers ========================================
__device__ __forceinline__ uint32_t smem_u32(const void* p) {
    uint32_t a;
    asm("{ .reg .u64 t; cvta.to.shared.u64 t, %1; cvt.u32.u64 %0, t; }" : "=r"(a) : "l"(p));
    return a;
}
__device__ __forceinline__ void ldmx4(uint32_t* r, uint32_t addr) {
    asm volatile("ldmatrix.sync.aligned.m8n8.x4.shared.b16 {%0,%1,%2,%3}, [%4];"
                 : "=r"(r[0]), "=r"(r[1]), "=r"(r[2]), "=r"(r[3]) : "r"(addr));
}
__device__ __forceinline__ void mma16816h(float* c, const uint32_t* a, const uint32_t* b) {
    asm volatile(
        "mma.sync.aligned.m16n8k16.row.col.f32.f16.f16.f32 "
        "{%0,%1,%2,%3}, {%4,%5,%6,%7}, {%8,%9}, {%0,%1,%2,%3};"
        : "+f"(c[0]), "+f"(c[1]), "+f"(c[2]), "+f"(c[3])
        : "r"(a[0]), "r"(a[1]), "r"(a[2]), "r"(a[3]), "r"(b[0]), "r"(b[1]));
}
__device__ __forceinline__ uint32_t packh2(float a, float b) {
    __half2 p = __floats2half2_rn(a, b);
    return *(uint32_t*)&p;
}

// ====================== setup kernels ========================================
// 2 edges per thread (independent chains -> 2x MLP on atomic latency)
__global__ void k_degree(const int* __restrict__ ei) {
    int t = blockIdx.x * blockDim.x + threadIdx.x;
    if (t < NEH) {
        int d0 = ei[NE + t];
        int d1 = ei[NE + NEH + t];
        atomicAdd(&g_deg[d0], 1);
        atomicAdd(&g_deg[d1], 1);
    }
}
__global__ void k_scan1(int n) {
    __shared__ int wsum[32];
    int t = threadIdx.x;
    int gid = blockIdx.x * 1024 + t;
    int v = (gid < n) ? g_deg[gid] : 0;
    if (gid < n) {
        float d = (float)(v + 1);
        g_dinv[gid]   = rsqrtf(d);
        g_invdeg[gid] = 1.0f / d;
    }
    int x = v;
    #pragma unroll
    for (int o = 1; o < 32; o <<= 1) {
        int y = __shfl_up_sync(0xffffffffu, x, o);
        if ((t & 31) >= o) x += y;
    }
    if ((t & 31) == 31) wsum[t >> 5] = x;
    __syncthreads();
    if (t < 32) {
        int w = wsum[t];
        int xx = w;
        #pragma unroll
        for (int o = 1; o < 32; o <<= 1) {
            int y = __shfl_up_sync(0xffffffffu, xx, o);
            if (t >= o) xx += y;
        }
        wsum[t] = xx - w;
    }
    __syncthreads();
    int excl = x - v + wsum[t >> 5];
    if (gid < n) g_off[gid] = excl;
    if (t == 1023) g_bsum[blockIdx.x] = excl + v;
}
__global__ void k_scan3(int n, int nb) {
    __shared__ int s[128];
    int t = threadIdx.x;
    if (t < 128) s[t] = (t < nb) ? g_bsum[t] : 0;
    __syncthreads();
    #pragma unroll
    for (int o = 1; o < 128; o <<= 1) {
        int x = 0;
        if (t < 128 && t >= o) x = s[t - o];
        __syncthreads();
        if (t < 128) s[t] += x;
        __syncthreads();
    }
    int base = (blockIdx.x == 0) ? 0 : s[blockIdx.x - 1];
    int gid = blockIdx.x * 1024 + t;
    if (gid < n) {
        int v = g_off[gid] + base;
        g_off[gid]    = v;
        g_cursor[gid] = v;
    }
    if (gid == 0) g_off[n] = NE;
}
// 2 edges per thread scatter (independent atomic/store chains)
__global__ void k_scatter(const int* __restrict__ ei) {
    int t = blockIdx.x * blockDim.x + threadIdx.x;
    if (t < NEH) {
        int s0 = ei[t];
        int d0 = ei[NE + t];
        int s1 = ei[NEH + t];
        int d1 = ei[NE + NEH + t];
        float nm0 = g_dinv[s0] * g_dinv[d0];
        float nm1 = g_dinv[s1] * g_dinv[d1];
        int p0 = atomicAdd(&g_cursor[d0], 1);
        int p1 = atomicAdd(&g_cursor[d1], 1);
        g_csrn[p0] = make_int2(s0, __float_as_int(nm0));
        g_csrn[p1] = make_int2(s1, __float_as_int(nm1));
    }
}

// ====================== W prep: both weights, one kernel =====================
__device__ __forceinline__ void prep_frag(const float* W, uint2* frag, int idx, int N) {
    int NT = N / 8;
    int lane = idx & 31;
    int nt   = (idx >> 5) % NT;
    int ks   = idx / (32 * NT);
    int n = nt * 8 + (lane >> 2);
    int k = ks * 16 + (lane & 3) * 2;
    uint2 o;
    o.x = packh2(W[(k    ) * N + n], W[(k + 1) * N + n]);
    o.y = packh2(W[(k + 8) * N + n], W[(k + 9) * N + n]);
    frag[idx] = o;
}
__global__ void k_prepw_all(const float* __restrict__ W1, uint2* __restrict__ f1,
                            const float* __restrict__ W2, uint2* __restrict__ f2) {
    int idx = blockIdx.x * blockDim.x + threadIdx.x;
    const int N1 = 8 * 16 * 32;
    const int N2 = 8 * 8 * 32;
    if (idx < N1) prep_frag(W1, f1, idx, 128);
    else if (idx < N1 + N2) prep_frag(W2, f2, idx - N1, 64);
}

// ====================== gemm1: C[M,128] = fp16(A_fp32) @ W1, 1-term ==========
__global__ void __launch_bounds__(256, 3) k_gemm1(
    const float* __restrict__ A,
    const uint2* __restrict__ Wf,
    __half* __restrict__ C, int M) {
    const int N = 128, SP = 136, NS = 4, NT = 16;
    extern __shared__ __align__(16) __half sm[];
    __half* As = sm;

    int tid = threadIdx.x, lane = tid & 31, wid = tid >> 5;
    int row0 = blockIdx.x * 64;

    #pragma unroll
    for (int i = tid; i < 2048; i += 256) {
        int r  = i >> 5;
        int c4 = (i & 31) << 2;
        int row = row0 + r;
        float4 v = (row < M) ? *(const float4*)(A + (size_t)row * 128 + c4)
                             : make_float4(0.f, 0.f, 0.f, 0.f);
        *(uint2*)(As + r * SP + c4) = make_uint2(packh2(v.x, v.y), packh2(v.z, v.w));
    }
    __syncthreads();

    int wm  = (wid >> 2) * 32;
    int wnt = (wid & 3) * NS;

    float acc[2][NS][4];
    #pragma unroll
    for (int ms = 0; ms < 2; ms++)
        #pragma unroll
        for (int ns = 0; ns < NS; ns++)
            #pragma unroll
            for (int q = 0; q < 4; q++) acc[ms][ns][q] = 0.f;

    uint32_t base_a = smem_u32(As);

    #pragma unroll
    for (int k0 = 0; k0 < 128; k0 += 16) {
        int ks = k0 >> 4;
        uint32_t a[2][4];
        #pragma unroll
        for (int ms = 0; ms < 2; ms++) {
            int ar = wm + ms * 16 + (lane & 15);
            int ac = k0 + (lane >> 4) * 8;
            uint32_t off = (uint32_t)(ar * SP + ac) * 2;
            ldmx4(a[ms], base_a + off);
        }
        const uint2* fp = Wf + ((size_t)ks * NT + wnt) * 32 + lane;
        #pragma unroll
        for (int ns = 0; ns < NS; ns++) {
            uint2 f = __ldg(fp + ns * 32);
            uint32_t b[2] = {f.x, f.y};
            mma16816h(acc[0][ns], a[0], b);
            mma16816h(acc[1][ns], a[1], b);
        }
    }

    int gID = lane >> 2, tig = lane & 3;
    #pragma unroll
    for (int ms = 0; ms < 2; ms++) {
        int r0 = row0 + wm + ms * 16 + gID;
        #pragma unroll
        for (int ns = 0; ns < NS; ns++) {
            int col = (wnt + ns) * 8 + tig * 2;
            if (r0 < M)
                *(__half2*)(C + (size_t)r0 * N + col) =
                    __floats2half2_rn(acc[ms][ns][0], acc[ms][ns][1]);
            if (r0 + 8 < M)
                *(__half2*)(C + (size_t)(r0 + 8) * N + col) =
                    __floats2half2_rn(acc[ms][ns][2], acc[ms][ns][3]);
        }
    }
}

// ====================== gemm2: C[M,64] = A_fp16[M,128] @ W2, 1-term ==========
__global__ void __launch_bounds__(256, 3) k_gemm2(
    const __half* __restrict__ A,
    const uint2* __restrict__ Wf,
    __half* __restrict__ C, int M) {
    const int N = 64, SP = 136, NS = 2, NT = 8;
    extern __shared__ __align__(16) __half sm[];
    __half* As = sm;

    int tid = threadIdx.x, lane = tid & 31, wid = tid >> 5;
    int row0 = blockIdx.x * 64;

    #pragma unroll
    for (int i = tid; i < 1024; i += 256) {
        int r  = i >> 4;
        int c8 = (i & 15) << 3;
        int row = row0 + r;
        uint4 v = (row < M) ? *(const uint4*)(A + (size_t)row * 128 + c8)
                            : make_uint4(0u, 0u, 0u, 0u);
        *(uint4*)(As + r * SP + c8) = v;
    }
    __syncthreads();

    int wm  = (wid >> 2) * 32;
    int wnt = (wid & 3) * NS;

    float acc[2][NS][4];
    #pragma unroll
    for (int ms = 0; ms < 2; ms++)
        #pragma unroll
        for (int ns = 0; ns < NS; ns++)
            #pragma unroll
            for (int q = 0; q < 4; q++) acc[ms][ns][q] = 0.f;

    uint32_t base_a = smem_u32(As);

    #pragma unroll
    for (int k0 = 0; k0 < 128; k0 += 16) {
        int ks = k0 >> 4;
        uint32_t a[2][4];
        #pragma unroll
        for (int ms = 0; ms < 2; ms++) {
            int ar = wm + ms * 16 + (lane & 15);
            int ac = k0 + (lane >> 4) * 8;
            uint32_t off = (uint32_t)(ar * SP + ac) * 2;
            ldmx4(a[ms], base_a + off);
        }
        const uint2* fp = Wf + ((size_t)ks * NT + wnt) * 32 + lane;
        #pragma unroll
        for (int ns = 0; ns < NS; ns++) {
            uint2 f = __ldg(fp + ns * 32);
            uint32_t b[2] = {f.x, f.y};
            mma16816h(acc[0][ns], a[0], b);
            mma16816h(acc[1][ns], a[1], b);
        }
    }

    int gID = lane >> 2, tig = lane & 3;
    #pragma unroll
    for (int ms = 0; ms < 2; ms++) {
        int r0 = row0 + wm + ms * 16 + gID;
        #pragma unroll
        for (int ns = 0; ns < NS; ns++) {
            int col = (wnt + ns) * 8 + tig * 2;
            if (r0 < M)
                *(__half2*)(C + (size_t)r0 * N + col) =
                    __floats2half2_rn(acc[ms][ns][0], acc[ms][ns][1]);
            if (r0 + 8 < M)
                *(__half2*)(C + (size_t)(r0 + 8) * N + col) =
                    __floats2half2_rn(acc[ms][ns][2], acc[ms][ns][3]);
        }
    }
}

// ====================== aggregation: one warp per node, 4-wide MLP ===========
template <int D, bool RELU>
__global__ void k_agg(const __half* __restrict__ h, const float* __restrict__ bias,
                      __half* __restrict__ zo) {
    int w    = (blockIdx.x * blockDim.x + threadIdx.x) >> 5;
    int lane = threadIdx.x & 31;
    if (w >= NN) return;
    const int V = D / 32;
    int beg = g_off[w], end = g_off[w + 1];
    float acc[V];
    #pragma unroll
    for (int i = 0; i < V; i++) acc[i] = 0.0f;

    for (int bb = beg; bb < end; bb += 32) {
        int e = bb + lane;
        int2 sn = (e < end) ? g_csrn[e] : make_int2(0, 0);
        int s = sn.x;
        float nm = __int_as_float(sn.y);
        int cnt = min(32, end - bb);
        int j = 0;
        for (; j + 3 < cnt; j += 4) {
            int   s0 = __shfl_sync(0xffffffffu, s,  j);
            float n0 = __shfl_sync(0xffffffffu, nm, j);
            int   s1 = __shfl_sync(0xffffffffu, s,  j + 1);
            float n1 = __shfl_sync(0xffffffffu, nm, j + 1);
            int   s2 = __shfl_sync(0xffffffffu, s,  j + 2);
            float n2 = __shfl_sync(0xffffffffu, nm, j + 2);
            int   s3 = __shfl_sync(0xffffffffu, s,  j + 3);
            float n3 = __shfl_sync(0xffffffffu, nm, j + 3);
            if (V == 4) {
                uint2 u0 = *(const uint2*)(h + (size_t)s0 * D + lane * 4);
                uint2 u1 = *(const uint2*)(h + (size_t)s1 * D + lane * 4);
                uint2 u2 = *(const uint2*)(h + (size_t)s2 * D + lane * 4);
                uint2 u3 = *(const uint2*)(h + (size_t)s3 * D + lane * 4);
                float2 a0 = __half22float2(*(__half2*)&u0.x), b0 = __half22float2(*(__half2*)&u0.y);
                float2 a1 = __half22float2(*(__half2*)&u1.x), b1 = __half22float2(*(__half2*)&u1.y);
                float2 a2 = __half22float2(*(__half2*)&u2.x), b2 = __half22float2(*(__half2*)&u2.y);
                float2 a3 = __half22float2(*(__half2*)&u3.x), b3 = __half22float2(*(__half2*)&u3.y);
                acc[0] += a0.x * n0; acc[1] += a0.y * n0; acc[2] += b0.x * n0; acc[3] += b0.y * n0;
                acc[0] += a1.x * n1; acc[1] += a1.y * n1; acc[2] += b1.x * n1; acc[3] += b1.y * n1;
                acc[0] += a2.x * n2; acc[1] += a2.y * n2; acc[2] += b2.x * n2; acc[3] += b2.y * n2;
                acc[0] += a3.x * n3; acc[1] += a3.y * n3; acc[2] += b3.x * n3; acc[3] += b3.y * n3;
            } else {
                uint32_t u0 = *(const uint32_t*)(h + (size_t)s0 * D + lane * 2);
                uint32_t u1 = *(const uint32_t*)(h + (size_t)s1 * D + lane * 2);
                uint32_t u2 = *(const uint32_t*)(h + (size_t)s2 * D + lane * 2);
                uint32_t u3 = *(const uint32_t*)(h + (size_t)s3 * D + lane * 2);
                float2 a0 = __half22float2(*(__half2*)&u0);
                float2 a1 = __half22float2(*(__half2*)&u1);
                float2 a2 = __half22float2(*(__half2*)&u2);
                float2 a3 = __half22float2(*(__half2*)&u3);
                acc[0] += a0.x * n0; acc[1] += a0.y * n0;
                acc[0] += a1.x * n1; acc[1] += a1.y * n1;
                acc[0] += a2.x * n2; acc[1] += a2.y * n2;
                acc[0] += a3.x * n3; acc[1] += a3.y * n3;
            }
        }
        for (; j < cnt; j++) {
            int   s0 = __shfl_sync(0xffffffffu, s,  j);
            float n0 = __shfl_sync(0xffffffffu, nm, j);
            const __half* p0 = h + (size_t)s0 * D + lane * V;
            if (V == 4) {
                uint2 u0 = *(const uint2*)p0;
                float2 a0 = __half22float2(*(__half2*)&u0.x);
                float2 b0 = __half22float2(*(__half2*)&u0.y);
                acc[0] += a0.x * n0; acc[1] += a0.y * n0;
                acc[2] += b0.x * n0; acc[3] += b0.y * n0;
            } else {
                uint32_t u0 = *(const uint32_t*)p0;
                float2 a0 = __half22float2(*(__half2*)&u0);
                acc[0] += a0.x * n0; acc[1] += a0.y * n0;
            }
        }
    }

    float inv = g_invdeg[w];
    const __half* hp = h + (size_t)w * D + lane * V;
    const float* bp = bias + lane * V;
    __half* op = zo + (size_t)w * D + lane * V;
    if (V == 4) {
        uint2 su = *(const uint2*)hp;
        float2 s0 = __half22float2(*(__half2*)&su.x);
        float2 s1 = __half22float2(*(__half2*)&su.y);
        float4 bv = *(const float4*)bp;
        float ox = acc[0] + s0.x * inv + bv.x;
        float oy = acc[1] + s0.y * inv + bv.y;
        float oz = acc[2] + s1.x * inv + bv.z;
        float ow = acc[3] + s1.y * inv + bv.w;
        if (RELU) { ox = fmaxf(ox, 0.f); oy = fmaxf(oy, 0.f);
                    oz = fmaxf(oz, 0.f); ow = fmaxf(ow, 0.f); }
        *(uint2*)op = make_uint2(packh2(ox, oy), packh2(oz, ow));
    } else {
        uint32_t su = *(const uint32_t*)hp;
        float2 s0 = __half22float2(*(__half2*)&su);
        float2 bv = *(const float2*)bp;
        float ox = acc[0] + s0.x * inv + bv.x;
        float oy = acc[1] + s0.y * inv + bv.y;
        if (RELU) { ox = fmaxf(ox, 0.f); oy = fmaxf(oy, 0.f); }
        *(uint32_t*)op = packh2(ox, oy);
    }
}

// ====================== decode: fp16 z2, 16 lanes per edge ===================
__global__ void k_decode(const int* __restrict__ li, float* __restrict__ out) {
    int gid = blockIdx.x * blockDim.x + threadIdx.x;
    int e = gid >> 4;
    int l = gid & 15;
    if (e >= NL) return;
    int a = li[e];
    int b = li[NL + e];
    uint2 ua = *(const uint2*)(g_z2 + (size_t)a * DOUT + l * 4);
    uint2 ub = *(const uint2*)(g_z2 + (size_t)b * DOUT + l * 4);
    float2 a0 = __half22float2(*(__half2*)&ua.x);
    float2 a1 = __half22float2(*(__half2*)&ua.y);
    float2 b0 = __half22float2(*(__half2*)&ub.x);
    float2 b1 = __half22float2(*(__half2*)&ub.y);
    float d = a0.x * b0.x + a0.y * b0.y + a1.x * b1.x + a1.y * b1.y;
    d += __shfl_xor_sync(0xffffffffu, d, 1);
    d += __shfl_xor_sync(0xffffffffu, d, 2);
    d += __shfl_xor_sync(0xffffffffu, d, 4);
    d += __shfl_xor_sync(0xffffffffu, d, 8);
    if (l == 0) out[e] = d;
}

// ====================== launch ===============================================
extern "C" void kernel_launch(void* const* d_in, const int* in_sizes, int n_in,
                              void* d_out, int out_size) {
    const float* x   = (const float*)d_in[0];
    const int*   ei  = (const int*)d_in[1];
    const int*   eli = (const int*)d_in[2];
    const float* W1  = (const float*)d_in[3];
    const float* b1  = (const float*)d_in[4];
    const float* W2  = (const float*)d_in[5];
    const float* b2  = (const float*)d_in[6];
    float* out = (float*)d_out;

    __half *p_h1, *p_z, *p_h2, *p_z2;
    uint2 *p_wf1, *p_wf2;
    int* p_deg;
    cudaGetSymbolAddress((void**)&p_h1, g_h1);
    cudaGetSymbolAddress((void**)&p_z,  g_z);
    cudaGetSymbolAddress((void**)&p_h2, g_h2);
    cudaGetSymbolAddress((void**)&p_z2, g_z2);
    cudaGetSymbolAddress((void**)&p_wf1, g_wf1);
    cudaGetSymbolAddress((void**)&p_wf2, g_wf2);
    cudaGetSymbolAddress((void**)&p_deg, g_deg);

    const int SP = 136;
    const int SMEM1 = 64 * SP * 2;
    const int SMEM2 = 64 * SP * 2;
    cudaFuncSetAttribute(k_gemm1, cudaFuncAttributeMaxDynamicSharedMemorySize, SMEM1);
    cudaFuncSetAttribute(k_gemm2, cudaFuncAttributeMaxDynamicSharedMemorySize, SMEM2);

    const int NB_EDGE2 = (NEH + 255) / 256;      // 3125 (2 edges/thread)
    const int NB_SCAN  = (NN + 1023) / 1024;
    const int NB_GEMM1 = (NN + 63) / 64;
    const int NB_GEMM2 = (NN + 63) / 64;
    const int NB_AGG   = (NN * 32 + 511) / 512;  // 512-thread blocks
    const int NB_DEC   = (NL * 16 + 255) / 256;

    cudaStream_t s2;
    cudaStreamCreateWithFlags(&s2, cudaStreamNonBlocking);
    cudaEvent_t evF, evJ;
    cudaEventCreateWithFlags(&evF, cudaEventDisableTiming);
    cudaEventCreateWithFlags(&evJ, cudaEventDisableTiming);

    cudaEventRecord(evF, 0);
    cudaStreamWaitEvent(s2, evF, 0);

    // setup chain on s2
    cudaMemsetAsync(p_deg, 0, NN * sizeof(int), s2);
    k_degree<<<NB_EDGE2, 256, 0, s2>>>(ei);
    k_scan1<<<NB_SCAN, 1024, 0, s2>>>(NN);
    k_scan3<<<NB_SCAN, 1024, 0, s2>>>(NN, NB_SCAN);
    k_scatter<<<NB_EDGE2, 256, 0, s2>>>(ei);
    cudaEventRecord(evJ, s2);

    // main stream: W prep + gemm1
    k_prepw_all<<<(6144 + 255) / 256, 256>>>(W1, p_wf1, W2, p_wf2);
    k_gemm1<<<NB_GEMM1, 256, SMEM1>>>(x, p_wf1, p_h1, NN);

    cudaStreamWaitEvent(0, evJ, 0);

    k_agg<DH, true><<<NB_AGG, 512>>>(p_h1, b1, p_z);           // z = relu(Ah1+b1)
    k_gemm2<<<NB_GEMM2, 256, SMEM2>>>(p_z, p_wf2, p_h2, NN);   // h2 = z @ W2
    k_agg<DOUT, false><<<NB_AGG, 512>>>(p_h2, b2, p_z2);       // z2 = Ah2+b2
    k_decode<<<NB_DEC, 256>>>(eli, out);
}

// round 17
// speedup vs baseline: 1.3190x; 1.0430x over previous
#include <cuda_runtime.h>
#include <cuda_fp16.h>
#include <cstdint>

#define NN 100000
#define NE 1600000
#define NL 200000
#define DH  128
#define DOUT 64

// ====================== scratch (device globals) =============================
__device__ __align__(16) int   g_deg[NN];
__device__ __align__(16) float g_dinv[NN];
__device__ __align__(16) float g_invdeg[NN];
__device__ __align__(16) int   g_off[NN + 1];
__device__ __align__(16) int   g_cursor[NN];
__device__ __align__(16) int2  g_csrn[NE];               // {src, norm bits}
__device__ __align__(16) int   g_bsum[128];
__device__ __align__(16) __half g_h1[(size_t)NN * DH];
__device__ __align__(16) __half g_z [(size_t)NN * DH];
__device__ __align__(16) __half g_h2[(size_t)NN * DOUT];
__device__ __align__(16) __half g_z2[(size_t)NN * DOUT];
// W fragments (fp16), mma-ready: [ks][ntile][lane] -> uint2{b0,b1}
__device__ __align__(16) uint2 g_wf1[8 * 16 * 32];
__device__ __align__(16) uint2 g_wf2[8 * 8 * 32];

// ====================== small helpers ========================================
__device__ __forceinline__ uint32_t smem_u32(const void* p) {
    uint32_t a;
    asm("{ .reg .u64 t; cvta.to.shared.u64 t, %1; cvt.u32.u64 %0, t; }" : "=r"(a) : "l"(p));
    return a;
}
__device__ __forceinline__ void ldmx4(uint32_t* r, uint32_t addr) {
    asm volatile("ldmatrix.sync.aligned.m8n8.x4.shared.b16 {%0,%1,%2,%3}, [%4];"
                 : "=r"(r[0]), "=r"(r[1]), "=r"(r[2]), "=r"(r[3]) : "r"(addr));
}
__device__ __forceinline__ void mma16816h(float* c, const uint32_t* a, const uint32_t* b) {
    asm volatile(
        "mma.sync.aligned.m16n8k16.row.col.f32.f16.f16.f32 "
        "{%0,%1,%2,%3}, {%4,%5,%6,%7}, {%8,%9}, {%0,%1,%2,%3};"
        : "+f"(c[0]), "+f"(c[1]), "+f"(c[2]), "+f"(c[3])
        : "r"(a[0]), "r"(a[1]), "r"(a[2]), "r"(a[3]), "r"(b[0]), "r"(b[1]));
}
__device__ __forceinline__ uint32_t packh2(float a, float b) {
    __half2 p = __floats2half2_rn(a, b);
    return *(uint32_t*)&p;
}

// ====================== setup kernels (R12 form) ==============================
__global__ void k_degree(const int* __restrict__ ei) {
    int e = blockIdx.x * blockDim.x + threadIdx.x;
    if (e < NE) atomicAdd(&g_deg[ei[NE + e]], 1);
}
__global__ void k_scan1(int n) {
    __shared__ int wsum[32];
    int t = threadIdx.x;
    int gid = blockIdx.x * 1024 + t;
    int v = (gid < n) ? g_deg[gid] : 0;
    if (gid < n) {
        float d = (float)(v + 1);
        g_dinv[gid]   = rsqrtf(d);
        g_invdeg[gid] = 1.0f / d;
    }
    int x = v;
    #pragma unroll
    for (int o = 1; o < 32; o <<= 1) {
        int y = __shfl_up_sync(0xffffffffu, x, o);
        if ((t & 31) >= o) x += y;
    }
    if ((t & 31) == 31) wsum[t >> 5] = x;
    __syncthreads();
    if (t < 32) {
        int w = wsum[t];
        int xx = w;
        #pragma unroll
        for (int o = 1; o < 32; o <<= 1) {
            int y = __shfl_up_sync(0xffffffffu, xx, o);
            if (t >= o) xx += y;
        }
        wsum[t] = xx - w;
    }
    __syncthreads();
    int excl = x - v + wsum[t >> 5];
    if (gid < n) g_off[gid] = excl;
    if (t == 1023) g_bsum[blockIdx.x] = excl + v;
}
__global__ void k_scan3(int n, int nb) {
    __shared__ int s[128];
    int t = threadIdx.x;
    if (t < 128) s[t] = (t < nb) ? g_bsum[t] : 0;
    __syncthreads();
    #pragma unroll
    for (int o = 1; o < 128; o <<= 1) {
        int x = 0;
        if (t < 128 && t >= o) x = s[t - o];
        __syncthreads();
        if (t < 128) s[t] += x;
        __syncthreads();
    }
    int base = (blockIdx.x == 0) ? 0 : s[blockIdx.x - 1];
    int gid = blockIdx.x * 1024 + t;
    if (gid < n) {
        int v = g_off[gid] + base;
        g_off[gid]    = v;
        g_cursor[gid] = v;
    }
    if (gid == 0) g_off[n] = NE;
}
__global__ void k_scatter(const int* __restrict__ ei) {
    int e = blockIdx.x * blockDim.x + threadIdx.x;
    if (e < NE) {
        int s = ei[e];
        int d = ei[NE + e];
        float nm = g_dinv[s] * g_dinv[d];
        int p = atomicAdd(&g_cursor[d], 1);
        g_csrn[p] = make_int2(s, __float_as_int(nm));
    }
}

// ====================== W prep: both weights, one kernel =====================
__device__ __forceinline__ void prep_frag(const float* W, uint2* frag, int idx, int N) {
    int NT = N / 8;
    int lane = idx & 31;
    int nt   = (idx >> 5) % NT;
    int ks   = idx / (32 * NT);
    int n = nt * 8 + (lane >> 2);
    int k = ks * 16 + (lane & 3) * 2;
    uint2 o;
    o.x = packh2(W[(k    ) * N + n], W[(k + 1) * N + n]);
    o.y = packh2(W[(k + 8) * N + n], W[(k + 9) * N + n]);
    frag[idx] = o;
}
__global__ void k_prepw_all(const float* __restrict__ W1, uint2* __restrict__ f1,
                            const float* __restrict__ W2, uint2* __restrict__ f2) {
    int idx = blockIdx.x * blockDim.x + threadIdx.x;
    const int N1 = 8 * 16 * 32;
    const int N2 = 8 * 8 * 32;
    if (idx < N1) prep_frag(W1, f1, idx, 128);
    else if (idx < N1 + N2) prep_frag(W2, f2, idx - N1, 64);
}

// ====================== gemm1: C[M,128] = fp16(A_fp32) @ W1, 1-term ==========
__global__ void __launch_bounds__(256, 3) k_gemm1(
    const float* __restrict__ A,
    const uint2* __restrict__ Wf,
    __half* __restrict__ C, int M) {
    const int N = 128, SP = 136, NS = 4, NT = 16;
    extern __shared__ __align__(16) __half sm[];
    __half* As = sm;

    int tid = threadIdx.x, lane = tid & 31, wid = tid >> 5;
    int row0 = blockIdx.x * 64;

    #pragma unroll
    for (int i = tid; i < 2048; i += 256) {
        int r  = i >> 5;
        int c4 = (i & 31) << 2;
        int row = row0 + r;
        float4 v = (row < M) ? *(const float4*)(A + (size_t)row * 128 + c4)
                             : make_float4(0.f, 0.f, 0.f, 0.f);
        *(uint2*)(As + r * SP + c4) = make_uint2(packh2(v.x, v.y), packh2(v.z, v.w));
    }
    __syncthreads();

    int wm  = (wid >> 2) * 32;
    int wnt = (wid & 3) * NS;

    float acc[2][NS][4];
    #pragma unroll
    for (int ms = 0; ms < 2; ms++)
        #pragma unroll
        for (int ns = 0; ns < NS; ns++)
            #pragma unroll
            for (int q = 0; q < 4; q++) acc[ms][ns][q] = 0.f;

    uint32_t base_a = smem_u32(As);

    #pragma unroll
    for (int k0 = 0; k0 < 128; k0 += 16) {
        int ks = k0 >> 4;
        uint32_t a[2][4];
        #pragma unroll
        for (int ms = 0; ms < 2; ms++) {
            int ar = wm + ms * 16 + (lane & 15);
            int ac = k0 + (lane >> 4) * 8;
            uint32_t off = (uint32_t)(ar * SP + ac) * 2;
            ldmx4(a[ms], base_a + off);
        }
        const uint2* fp = Wf + ((size_t)ks * NT + wnt) * 32 + lane;
        #pragma unroll
        for (int ns = 0; ns < NS; ns++) {
            uint2 f = __ldg(fp + ns * 32);
            uint32_t b[2] = {f.x, f.y};
            mma16816h(acc[0][ns], a[0], b);
            mma16816h(acc[1][ns], a[1], b);
        }
    }

    int gID = lane >> 2, tig = lane & 3;
    #pragma unroll
    for (int ms = 0; ms < 2; ms++) {
        int r0 = row0 + wm + ms * 16 + gID;
        #pragma unroll
        for (int ns = 0; ns < NS; ns++) {
            int col = (wnt + ns) * 8 + tig * 2;
            if (r0 < M)
                *(__half2*)(C + (size_t)r0 * N + col) =
                    __floats2half2_rn(acc[ms][ns][0], acc[ms][ns][1]);
            if (r0 + 8 < M)
                *(__half2*)(C + (size_t)(r0 + 8) * N + col) =
                    __floats2half2_rn(acc[ms][ns][2], acc[ms][ns][3]);
        }
    }
}

// ====================== gemm2: C[M,64] = A_fp16[M,128] @ W2, 1-term ==========
__global__ void __launch_bounds__(256, 3) k_gemm2(
    const __half* __restrict__ A,
    const uint2* __restrict__ Wf,
    __half* __restrict__ C, int M) {
    const int N = 64, SP = 136, NS = 2, NT = 8;
    extern __shared__ __align__(16) __half sm[];
    __half* As = sm;

    int tid = threadIdx.x, lane = tid & 31, wid = tid >> 5;
    int row0 = blockIdx.x * 64;

    #pragma unroll
    for (int i = tid; i < 1024; i += 256) {
        int r  = i >> 4;
        int c8 = (i & 15) << 3;
        int row = row0 + r;
        uint4 v = (row < M) ? *(const uint4*)(A + (size_t)row * 128 + c8)
                            : make_uint4(0u, 0u, 0u, 0u);
        *(uint4*)(As + r * SP + c8) = v;
    }
    __syncthreads();

    int wm  = (wid >> 2) * 32;
    int wnt = (wid & 3) * NS;

    float acc[2][NS][4];
    #pragma unroll
    for (int ms = 0; ms < 2; ms++)
        #pragma unroll
        for (int ns = 0; ns < NS; ns++)
            #pragma unroll
            for (int q = 0; q < 4; q++) acc[ms][ns][q] = 0.f;

    uint32_t base_a = smem_u32(As);

    #pragma unroll
    for (int k0 = 0; k0 < 128; k0 += 16) {
        int ks = k0 >> 4;
        uint32_t a[2][4];
        #pragma unroll
        for (int ms = 0; ms < 2; ms++) {
            int ar = wm + ms * 16 + (lane & 15);
            int ac = k0 + (lane >> 4) * 8;
            uint32_t off = (uint32_t)(ar * SP + ac) * 2;
            ldmx4(a[ms], base_a + off);
        }
        const uint2* fp = Wf + ((size_t)ks * NT + wnt) * 32 + lane;
        #pragma unroll
        for (int ns = 0; ns < NS; ns++) {
            uint2 f = __ldg(fp + ns * 32);
            uint32_t b[2] = {f.x, f.y};
            mma16816h(acc[0][ns], a[0], b);
            mma16816h(acc[1][ns], a[1], b);
        }
    }

    int gID = lane >> 2, tig = lane & 3;
    #pragma unroll
    for (int ms = 0; ms < 2; ms++) {
        int r0 = row0 + wm + ms * 16 + gID;
        #pragma unroll
        for (int ns = 0; ns < NS; ns++) {
            int col = (wnt + ns) * 8 + tig * 2;
            if (r0 < M)
                *(__half2*)(C + (size_t)r0 * N + col) =
                    __floats2half2_rn(acc[ms][ns][0], acc[ms][ns][1]);
            if (r0 + 8 < M)
                *(__half2*)(C + (size_t)(r0 + 8) * N + col) =
                    __floats2half2_rn(acc[ms][ns][2], acc[ms][ns][3]);
        }
    }
}

// ====================== aggregation: one warp per node, 4-wide MLP ===========
template <int D, bool RELU>
__global__ void k_agg(const __half* __restrict__ h, const float* __restrict__ bias,
                      __half* __restrict__ zo) {
    int w    = (blockIdx.x * blockDim.x + threadIdx.x) >> 5;
    int lane = threadIdx.x & 31;
    if (w >= NN) return;
    const int V = D / 32;
    int beg = g_off[w], end = g_off[w + 1];
    float acc[V];
    #pragma unroll
    for (int i = 0; i < V; i++) acc[i] = 0.0f;

    for (int bb = beg; bb < end; bb += 32) {
        int e = bb + lane;
        int2 sn = (e < end) ? g_csrn[e] : make_int2(0, 0);
        int s = sn.x;
        float nm = __int_as_float(sn.y);
        int cnt = min(32, end - bb);
        int j = 0;
        for (; j + 3 < cnt; j += 4) {
            int   s0 = __shfl_sync(0xffffffffu, s,  j);
            float n0 = __shfl_sync(0xffffffffu, nm, j);
            int   s1 = __shfl_sync(0xffffffffu, s,  j + 1);
            float n1 = __shfl_sync(0xffffffffu, nm, j + 1);
            int   s2 = __shfl_sync(0xffffffffu, s,  j + 2);
            float n2 = __shfl_sync(0xffffffffu, nm, j + 2);
            int   s3 = __shfl_sync(0xffffffffu, s,  j + 3);
            float n3 = __shfl_sync(0xffffffffu, nm, j + 3);
            if (V == 4) {
                uint2 u0 = *(const uint2*)(h + (size_t)s0 * D + lane * 4);
                uint2 u1 = *(const uint2*)(h + (size_t)s1 * D + lane * 4);
                uint2 u2 = *(const uint2*)(h + (size_t)s2 * D + lane * 4);
                uint2 u3 = *(const uint2*)(h + (size_t)s3 * D + lane * 4);
                float2 a0 = __half22float2(*(__half2*)&u0.x), b0 = __half22float2(*(__half2*)&u0.y);
                float2 a1 = __half22float2(*(__half2*)&u1.x), b1 = __half22float2(*(__half2*)&u1.y);
                float2 a2 = __half22float2(*(__half2*)&u2.x), b2 = __half22float2(*(__half2*)&u2.y);
                float2 a3 = __half22float2(*(__half2*)&u3.x), b3 = __half22float2(*(__half2*)&u3.y);
                acc[0] += a0.x * n0; acc[1] += a0.y * n0; acc[2] += b0.x * n0; acc[3] += b0.y * n0;
                acc[0] += a1.x * n1; acc[1] += a1.y * n1; acc[2] += b1.x * n1; acc[3] += b1.y * n1;
                acc[0] += a2.x * n2; acc[1] += a2.y * n2; acc[2] += b2.x * n2; acc[3] += b2.y * n2;
                acc[0] += a3.x * n3; acc[1] += a3.y * n3; acc[2] += b3.x * n3; acc[3] += b3.y * n3;
            } else {
                uint32_t u0 = *(const uint32_t*)(h + (size_t)s0 * D + lane * 2);
                uint32_t u1 = *(const uint32_t*)(h + (size_t)s1 * D + lane * 2);
                uint32_t u2 = *(const uint32_t*)(h + (size_t)s2 * D + lane * 2);
                uint32_t u3 = *(const uint32_t*)(h + (size_t)s3 * D + lane * 2);
                float2 a0 = __half22float2(*(__half2*)&u0);
                float2 a1 = __half22float2(*(__half2*)&u1);
                float2 a2 = __half22float2(*(__half2*)&u2);
                float2 a3 = __half22float2(*(__half2*)&u3);
                acc[0] += a0.x * n0; acc[1] += a0.y * n0;
                acc[0] += a1.x * n1; acc[1] += a1.y * n1;
                acc[0] += a2.x * n2; acc[1] += a2.y * n2;
                acc[0] += a3.x * n3; acc[1] += a3.y * n3;
            }
        }
        for (; j < cnt; j++) {
            int   s0 = __shfl_sync(0xffffffffu, s,  j);
            float n0 = __shfl_sync(0xffffffffu, nm, j);
            const __half* p0 = h + (size_t)s0 * D + lane * V;
            if (V == 4) {
                uint2 u0 = *(const uint2*)p0;
                float2 a0 = __half22float2(*(__half2*)&u0.x);
                float2 b0 = __half22float2(*(__half2*)&u0.y);
                acc[0] += a0.x * n0; acc[1] += a0.y * n0;
                acc[2] += b0.x * n0; acc[3] += b0.y * n0;
            } else {
                uint32_t u0 = *(const uint32_t*)p0;
                float2 a0 = __half22float2(*(__half2*)&u0);
                acc[0] += a0.x * n0; acc[1] += a0.y * n0;
            }
        }
    }

    float inv = g_invdeg[w];
    const __half* hp = h + (size_t)w * D + lane * V;
    const float* bp = bias + lane * V;
    __half* op = zo + (size_t)w * D + lane * V;
    if (V == 4) {
        uint2 su = *(const uint2*)hp;
        float2 s0 = __half22float2(*(__half2*)&su.x);
        float2 s1 = __half22float2(*(__half2*)&su.y);
        float4 bv = *(const float4*)bp;
        float ox = acc[0] + s0.x * inv + bv.x;
        float oy = acc[1] + s0.y * inv + bv.y;
        float oz = acc[2] + s1.x * inv + bv.z;
        float ow = acc[3] + s1.y * inv + bv.w;
        if (RELU) { ox = fmaxf(ox, 0.f); oy = fmaxf(oy, 0.f);
                    oz = fmaxf(oz, 0.f); ow = fmaxf(ow, 0.f); }
        *(uint2*)op = make_uint2(packh2(ox, oy), packh2(oz, ow));
    } else {
        uint32_t su = *(const uint32_t*)hp;
        float2 s0 = __half22float2(*(__half2*)&su);
        float2 bv = *(const float2*)bp;
        float ox = acc[0] + s0.x * inv + bv.x;
        float oy = acc[1] + s0.y * inv + bv.y;
        if (RELU) { ox = fmaxf(ox, 0.f); oy = fmaxf(oy, 0.f); }
        *(uint32_t*)op = packh2(ox, oy);
    }
}

// ====================== decode: fp16 z2, 16 lanes per edge ===================
__global__ void k_decode(const int* __restrict__ li, float* __restrict__ out) {
    int gid = blockIdx.x * blockDim.x + threadIdx.x;
    int e = gid >> 4;
    int l = gid & 15;
    if (e >= NL) return;
    int a = li[e];
    int b = li[NL + e];
    uint2 ua = *(const uint2*)(g_z2 + (size_t)a * DOUT + l * 4);
    uint2 ub = *(const uint2*)(g_z2 + (size_t)b * DOUT + l * 4);
    float2 a0 = __half22float2(*(__half2*)&ua.x);
    float2 a1 = __half22float2(*(__half2*)&ua.y);
    float2 b0 = __half22float2(*(__half2*)&ub.x);
    float2 b1 = __half22float2(*(__half2*)&ub.y);
    float d = a0.x * b0.x + a0.y * b0.y + a1.x * b1.x + a1.y * b1.y;
    d += __shfl_xor_sync(0xffffffffu, d, 1);
    d += __shfl_xor_sync(0xffffffffu, d, 2);
    d += __shfl_xor_sync(0xffffffffu, d, 4);
    d += __shfl_xor_sync(0xffffffffu, d, 8);
    if (l == 0) out[e] = d;
}

// ====================== launch ===============================================
extern "C" void kernel_launch(void* const* d_in, const int* in_sizes, int n_in,
                              void* d_out, int out_size) {
    const float* x   = (const float*)d_in[0];
    const int*   ei  = (const int*)d_in[1];
    const int*   eli = (const int*)d_in[2];
    const float* W1  = (const float*)d_in[3];
    const float* b1  = (const float*)d_in[4];
    const float* W2  = (const float*)d_in[5];
    const float* b2  = (const float*)d_in[6];
    float* out = (float*)d_out;

    __half *p_h1, *p_z, *p_h2, *p_z2;
    uint2 *p_wf1, *p_wf2;
    int* p_deg;
    cudaGetSymbolAddress((void**)&p_h1, g_h1);
    cudaGetSymbolAddress((void**)&p_z,  g_z);
    cudaGetSymbolAddress((void**)&p_h2, g_h2);
    cudaGetSymbolAddress((void**)&p_z2, g_z2);
    cudaGetSymbolAddress((void**)&p_wf1, g_wf1);
    cudaGetSymbolAddress((void**)&p_wf2, g_wf2);
    cudaGetSymbolAddress((void**)&p_deg, g_deg);

    const int SP = 136;
    const int SMEM1 = 64 * SP * 2;
    const int SMEM2 = 64 * SP * 2;
    cudaFuncSetAttribute(k_gemm1, cudaFuncAttributeMaxDynamicSharedMemorySize, SMEM1);
    cudaFuncSetAttribute(k_gemm2, cudaFuncAttributeMaxDynamicSharedMemorySize, SMEM2);
    // maximize L1D for the smem-free gather/scatter kernels
    cudaFuncSetAttribute(k_agg<DH, true>,   cudaFuncAttributePreferredSharedMemoryCarveout, 0);
    cudaFuncSetAttribute(k_agg<DOUT, false>,cudaFuncAttributePreferredSharedMemoryCarveout, 0);
    cudaFuncSetAttribute(k_scatter, cudaFuncAttributePreferredSharedMemoryCarveout, 0);
    cudaFuncSetAttribute(k_degree,  cudaFuncAttributePreferredSharedMemoryCarveout, 0);
    cudaFuncSetAttribute(k_decode,  cudaFuncAttributePreferredSharedMemoryCarveout, 0);

    const int NB_EDGE  = (NE + 255) / 256;
    const int NB_SCAN  = (NN + 1023) / 1024;
    const int NB_GEMM1 = (NN + 63) / 64;
    const int NB_GEMM2 = (NN + 63) / 64;
    const int NB_AGG   = (NN * 32 + 255) / 256;
    const int NB_DEC   = (NL * 16 + 255) / 256;

    cudaStream_t s2;
    cudaStreamCreateWithFlags(&s2, cudaStreamNonBlocking);
    cudaEvent_t evF, evJ;
    cudaEventCreateWithFlags(&evF, cudaEventDisableTiming);
    cudaEventCreateWithFlags(&evJ, cudaEventDisableTiming);

    cudaEventRecord(evF, 0);
    cudaStreamWaitEvent(s2, evF, 0);

    // setup chain on s2
    cudaMemsetAsync(p_deg, 0, NN * sizeof(int), s2);
    k_degree<<<NB_EDGE, 256, 0, s2>>>(ei);
    k_scan1<<<NB_SCAN, 1024, 0, s2>>>(NN);
    k_scan3<<<NB_SCAN, 1024, 0, s2>>>(NN, NB_SCAN);
    k_scatter<<<NB_EDGE, 256, 0, s2>>>(ei);
    cudaEventRecord(evJ, s2);

    // main stream: W prep + gemm1
    k_prepw_all<<<(6144 + 255) / 256, 256>>>(W1, p_wf1, W2, p_wf2);
    k_gemm1<<<NB_GEMM1, 256, SMEM1>>>(x, p_wf1, p_h1, NN);

    cudaStreamWaitEvent(0, evJ, 0);

    k_agg<DH, true><<<NB_AGG, 256>>>(p_h1, b1, p_z);           // z = relu(Ah1+b1)
    k_gemm2<<<NB_GEMM2, 256, SMEM2>>>(p_z, p_wf2, p_h2, NN);   // h2 = z @ W2
    k_agg<DOUT, false><<<NB_AGG, 256>>>(p_h2, b2, p_z2);       // z2 = Ah2+b2
    k_decode<<<NB_DEC, 256>>>(eli, out);
}